// round 12
// baseline (speedup 1.0000x reference)
#include <cuda_runtime.h>
#include <math.h>

typedef unsigned long long u64;

#define NSZ 192
#define NC  16
#define MXY 32
#define NLINE (NC*NSZ)       // 3072
#define NROW  (NC*NSZ*NSZ)   // 589824

// ---------------- packed f32x2 helpers --------------------------------------
__device__ __forceinline__ u64 pk2(float lo, float hi) {
  u64 r; asm("mov.b64 %0, {%1, %2};" : "=l"(r) : "f"(lo), "f"(hi)); return r;
}
__device__ __forceinline__ void up2(u64 v, float& lo, float& hi) {
  asm("mov.b64 {%0, %1}, %2;" : "=f"(lo), "=f"(hi) : "l"(v));
}
__device__ __forceinline__ u64 sw2(u64 v) {
  float a, b; up2(v, a, b); return pk2(b, a);
}
#define FMA2(d, a, b) asm("fma.rn.f32x2 %0, %1, %2, %0;" : "+l"(d) : "l"(a), "l"(b))

// ---------------- scratch ----------------------------------------------------
static __device__ float2 Tm[NSZ];
static __device__ u64 ftw1g[NSZ], ftw2g[NSZ];   // forward:  (c,c), (s,-s)
static __device__ u64 itw1g[NSZ], itw2g[NSZ];   // inverse:  (c,c), (-s,s)

static __device__ __align__(16) u64 X1g[(size_t)NROW * 16];
static __device__ __align__(16) u64 X2g[(size_t)NLINE * MXY * 16];
static __device__ __align__(16) u64 X3g[(size_t)NC * MXY * MXY * 16];
static __device__ __align__(16) u64 Y3g[(size_t)NC * MXY * MXY * 16];
static __device__ __align__(16) u64 Y2g[(size_t)NLINE * MXY * 16];
static __device__ __align__(16) u64 Y1g[(size_t)NROW * 16];

__device__ __forceinline__ int kmap(int j) { return j < 16 ? j : j + 160; }

// ---------------- init --------------------------------------------------------
__global__ void k_init() {
  int p = threadIdx.x;
  if (p < NSZ) {
    float s, c;
    sincosf(6.283185307179586f * (float)p / 192.0f, &s, &c);
    Tm[p] = make_float2(c, s);
    ftw1g[p] = pk2(c, c);  ftw2g[p] = pk2(s, -s);
    itw1g[p] = pk2(c, c);  itw2g[p] = pk2(-s, s);
  }
}

// ---------------- S1: z-DFT, real -> 16 complex modes (packed) ---------------
// acc(re,im) += (x,x) * (c,-s) : ONE FFMA2 per (z,kz) term.
__global__ void __launch_bounds__(128) k_s1(const float* __restrict__ xg) {
  __shared__ float xs[32 * 257];
  __shared__ u64 tws[32][16];          // (c, -s) packed
  int tid = threadIdx.x;
  int tx = tid & 3, ty = tid >> 2;
  int rowBase = blockIdx.x * 256;

  u64 acc[8][4];
#pragma unroll
  for (int j = 0; j < 8; j++)
#pragma unroll
    for (int q = 0; q < 4; q++) acc[j][q] = 0ULL;

  for (int zc = 0; zc < NSZ; zc += 32) {
    __syncthreads();
    for (int i = tid; i < 32 * 16; i += 128) {
      int zl = i >> 4, kz = i & 15;
      int p = (kz * (zc + zl)) % NSZ;
      float2 t = Tm[p];
      tws[zl][kz] = pk2(t.x, -t.y);
    }
    for (int i = tid; i < 256 * 8; i += 128) {
      int row = i >> 3, u = i & 7;
      float4 v = *(const float4*)(xg + (size_t)(rowBase + row) * NSZ + zc + 4 * u);
      int kb = 4 * u;
      xs[(kb + 0) * 257 + row] = v.x;
      xs[(kb + 1) * 257 + row] = v.y;
      xs[(kb + 2) * 257 + row] = v.z;
      xs[(kb + 3) * 257 + row] = v.w;
    }
    __syncthreads();
#pragma unroll 4
    for (int kk = 0; kk < 32; kk++) {
      u64 t0 = tws[kk][4 * tx + 0];
      u64 t1 = tws[kk][4 * tx + 1];
      u64 t2 = tws[kk][4 * tx + 2];
      u64 t3 = tws[kk][4 * tx + 3];
      const float* xr = &xs[kk * 257 + ty];
#pragma unroll
      for (int j = 0; j < 8; j++) {
        float xv = xr[32 * j];
        u64 xb = pk2(xv, xv);
        FMA2(acc[j][0], xb, t0);
        FMA2(acc[j][1], xb, t1);
        FMA2(acc[j][2], xb, t2);
        FMA2(acc[j][3], xb, t3);
      }
    }
  }
#pragma unroll
  for (int j = 0; j < 8; j++) {
    size_t base = (size_t)(rowBase + ty + 32 * j) * 16 + 4 * tx;
    ((ulonglong2*)&X1g[base])[0] = make_ulonglong2(acc[j][0], acc[j][1]);
    ((ulonglong2*)&X1g[base])[1] = make_ulonglong2(acc[j][2], acc[j][3]);
  }
}

// ---------------- S2: y-DFT, complex, 32 ky modes (packed) -------------------
__global__ void __launch_bounds__(128) k_s2() {
  __shared__ __align__(16) u64 x1s[4][48][16];
  __shared__ u64 tw1s[48][32], tw2s[48][32];
  int tid = threadIdx.x;
  int l = tid >> 5, lane = tid & 31;
  int kyg = lane >> 2, kzg = lane & 3;
  int lineBase = blockIdx.x * 4;

  u64 acc[4][4];
#pragma unroll
  for (int a = 0; a < 4; a++)
#pragma unroll
    for (int b = 0; b < 4; b++) acc[a][b] = 0ULL;

  for (int yc = 0; yc < NSZ; yc += 48) {
    __syncthreads();
    for (int i = tid; i < 48 * 32; i += 128) {
      int yl = i >> 5, ky = i & 31;
      int p = (kmap(ky) * (yc + yl)) % NSZ;
      tw1s[yl][ky] = ftw1g[p];
      tw2s[yl][ky] = ftw2g[p];
    }
    for (int i = tid; i < 4 * 48 * 8; i += 128) {
      int li = i / 384, rem = i % 384;
      int yl = rem >> 3, u = rem & 7;
      ((ulonglong2*)x1s[li][yl])[u] =
          ((const ulonglong2*)&X1g[((size_t)(lineBase + li) * NSZ + yc + yl) * 16])[u];
    }
    __syncthreads();
#pragma unroll 4
    for (int yy = 0; yy < 48; yy++) {
      ulonglong2 xa = ((ulonglong2*)&x1s[l][yy][4 * kzg])[0];
      ulonglong2 xb = ((ulonglong2*)&x1s[l][yy][4 * kzg])[1];
      u64 xv0 = xa.x, xv1 = xa.y, xv2 = xb.x, xv3 = xb.y;
      u64 xs0 = sw2(xv0), xs1 = sw2(xv1), xs2 = sw2(xv2), xs3 = sw2(xv3);
#pragma unroll
      for (int a = 0; a < 4; a++) {
        u64 w1 = tw1s[yy][4 * kyg + a];
        u64 w2 = tw2s[yy][4 * kyg + a];
        FMA2(acc[a][0], xv0, w1); FMA2(acc[a][0], xs0, w2);
        FMA2(acc[a][1], xv1, w1); FMA2(acc[a][1], xs1, w2);
        FMA2(acc[a][2], xv2, w1); FMA2(acc[a][2], xs2, w2);
        FMA2(acc[a][3], xv3, w1); FMA2(acc[a][3], xs3, w2);
      }
    }
  }
#pragma unroll
  for (int a = 0; a < 4; a++) {
    size_t base = ((size_t)(lineBase + l) * MXY + 4 * kyg + a) * 16 + 4 * kzg;
    ((ulonglong2*)&X2g[base])[0] = make_ulonglong2(acc[a][0], acc[a][1]);
    ((ulonglong2*)&X2g[base])[1] = make_ulonglong2(acc[a][2], acc[a][3]);
  }
}

// ---------------- S3: x-DFT, complex, 32 kx modes (packed) -------------------
// block per (c,ky); 128 thr = kx(32) x kzq(4 groups of 4 kz)
__global__ void __launch_bounds__(128) k_s3() {
  __shared__ __align__(16) u64 x2s[192][16];
  __shared__ u64 tw1l[NSZ], tw2l[NSZ];
  int c = blockIdx.x >> 5, ky = blockIdx.x & 31;
  int tid = threadIdx.x;
  int kx = tid & 31, kzq = tid >> 5;

  for (int i = tid; i < NSZ; i += 128) { tw1l[i] = ftw1g[i]; tw2l[i] = ftw2g[i]; }
  for (int i = tid; i < 192 * 8; i += 128) {
    int xx = i >> 3, u = i & 7;
    ((ulonglong2*)x2s[xx])[u] =
        ((const ulonglong2*)&X2g[(((size_t)c * NSZ + xx) * MXY + ky) * 16])[u];
  }
  __syncthreads();

  int kf = kmap(kx), p = 0;
  u64 a0 = 0, a1 = 0, a2 = 0, a3 = 0;
#pragma unroll 4
  for (int xx = 0; xx < NSZ; xx++) {
    u64 w1 = tw1l[p], w2 = tw2l[p];
    ulonglong2 va = ((ulonglong2*)&x2s[xx][4 * kzq])[0];
    ulonglong2 vb = ((ulonglong2*)&x2s[xx][4 * kzq])[1];
    FMA2(a0, va.x, w1); FMA2(a0, sw2(va.x), w2);
    FMA2(a1, va.y, w1); FMA2(a1, sw2(va.y), w2);
    FMA2(a2, vb.x, w1); FMA2(a2, sw2(vb.x), w2);
    FMA2(a3, vb.y, w1); FMA2(a3, sw2(vb.y), w2);
    p += kf; if (p >= NSZ) p -= NSZ;
  }
  size_t base = (((size_t)c * MXY + kx) * MXY + ky) * 16 + 4 * kzq;
  ((ulonglong2*)&X3g[base])[0] = make_ulonglong2(a0, a1);
  ((ulonglong2*)&X3g[base])[1] = make_ulonglong2(a2, a3);
}

// ---------------- Mix: 16x16 complex channel mix (packed) --------------------
__global__ void __launch_bounds__(256) k_mix(const float* __restrict__ wr,
                                             const float* __restrict__ wi) {
  __shared__ u64 xin[16][16], xsw[16][16];
  int kx = blockIdx.x >> 5, ky = blockIdx.x & 31;
  int tid = threadIdx.x;
  int kz = tid & 15, o = tid >> 4;
  {
    int i = tid >> 4, z = tid & 15;
    u64 v = X3g[(((size_t)i * MXY + kx) * MXY + ky) * 16 + z];
    xin[i][z] = v;
    xsw[i][z] = sw2(v);
  }
  __syncthreads();
  int q = (kx >= 16 ? 1 : 0) + (ky >= 16 ? 2 : 0);
  int mx = kx & 15, my = ky & 15;
  int moff = mx * 256 + my * 16 + kz;
  u64 acc = 0;
#pragma unroll
  for (int i = 0; i < 16; i++) {
    int widx = ((q * 16 + i) * 16 + o) * 4096 + moff;
    float wrv = wr[widx], wiv = wi[widx];
    FMA2(acc, xin[i][kz], pk2(wrv, wrv));
    FMA2(acc, xsw[i][kz], pk2(-wiv, wiv));
  }
  Y3g[(((size_t)o * MXY + kx) * MXY + ky) * 16 + kz] = acc;
}

// ---------------- I1: inverse x (32 modes -> 192 x), packed ------------------
// block per (c,ky); 192 thr, thread = x; 16 packed kz accumulators.
__global__ void __launch_bounds__(192) k_i1() {
  __shared__ __align__(16) u64 ysd[32][16], yswd[32][16];
  __shared__ u64 tw1l[NSZ], tw2l[NSZ];
  int c = blockIdx.x >> 5, ky = blockIdx.x & 31;
  int x = threadIdx.x;

  if (x < NSZ) { tw1l[x] = itw1g[x]; tw2l[x] = itw2g[x]; }
  for (int i = x; i < 512; i += 192) {
    int kx = i >> 4, z = i & 15;
    u64 v = Y3g[(((size_t)c * MXY + kx) * MXY + ky) * 16 + z];
    ysd[kx][z] = v;
    yswd[kx][z] = sw2(v);
  }
  __syncthreads();

  u64 acc[16];
#pragma unroll
  for (int z = 0; z < 16; z++) acc[z] = 0ULL;

  int p = 0;
#pragma unroll 2
  for (int kx = 0; kx < 16; kx++) {
    u64 w1 = tw1l[p], w2 = tw2l[p];
#pragma unroll
    for (int h = 0; h < 8; h++) {
      ulonglong2 y  = ((ulonglong2*)ysd[kx])[h];
      ulonglong2 ys = ((ulonglong2*)yswd[kx])[h];
      FMA2(acc[2 * h],     y.x,  w1); FMA2(acc[2 * h],     ys.x, w2);
      FMA2(acc[2 * h + 1], y.y,  w1); FMA2(acc[2 * h + 1], ys.y, w2);
    }
    p += x; if (p >= NSZ) p -= NSZ;
  }
  p = (176 * x) % NSZ;
#pragma unroll 2
  for (int kx = 16; kx < 32; kx++) {
    u64 w1 = tw1l[p], w2 = tw2l[p];
#pragma unroll
    for (int h = 0; h < 8; h++) {
      ulonglong2 y  = ((ulonglong2*)ysd[kx])[h];
      ulonglong2 ys = ((ulonglong2*)yswd[kx])[h];
      FMA2(acc[2 * h],     y.x,  w1); FMA2(acc[2 * h],     ys.x, w2);
      FMA2(acc[2 * h + 1], y.y,  w1); FMA2(acc[2 * h + 1], ys.y, w2);
    }
    p += x; if (p >= NSZ) p -= NSZ;
  }

  u64* dst = &Y2g[(((size_t)c * NSZ + x) * MXY + ky) * 16];
#pragma unroll
  for (int h = 0; h < 8; h++)
    ((ulonglong2*)dst)[h] = make_ulonglong2(acc[2 * h], acc[2 * h + 1]);
}

// ---------------- I2: inverse y (32 modes -> 192 y), packed ------------------
// block per line (c,x); 192 thr, thread = y.
__global__ void __launch_bounds__(192) k_i2() {
  __shared__ __align__(16) u64 ysd[32][16], yswd[32][16];
  __shared__ u64 tw1l[NSZ], tw2l[NSZ];
  size_t line = (size_t)blockIdx.x;
  int y = threadIdx.x;

  if (y < NSZ) { tw1l[y] = itw1g[y]; tw2l[y] = itw2g[y]; }
  for (int i = y; i < 512; i += 192) {
    u64 v = Y2g[line * 512 + i];
    ysd[i >> 4][i & 15] = v;
    yswd[i >> 4][i & 15] = sw2(v);
  }
  __syncthreads();

  u64 acc[16];
#pragma unroll
  for (int z = 0; z < 16; z++) acc[z] = 0ULL;

  int p = 0;
#pragma unroll 2
  for (int ky = 0; ky < 16; ky++) {
    u64 w1 = tw1l[p], w2 = tw2l[p];
#pragma unroll
    for (int h = 0; h < 8; h++) {
      ulonglong2 yv = ((ulonglong2*)ysd[ky])[h];
      ulonglong2 ys = ((ulonglong2*)yswd[ky])[h];
      FMA2(acc[2 * h],     yv.x, w1); FMA2(acc[2 * h],     ys.x, w2);
      FMA2(acc[2 * h + 1], yv.y, w1); FMA2(acc[2 * h + 1], ys.y, w2);
    }
    p += y; if (p >= NSZ) p -= NSZ;
  }
  p = (176 * y) % NSZ;
#pragma unroll 2
  for (int ky = 16; ky < 32; ky++) {
    u64 w1 = tw1l[p], w2 = tw2l[p];
#pragma unroll
    for (int h = 0; h < 8; h++) {
      ulonglong2 yv = ((ulonglong2*)ysd[ky])[h];
      ulonglong2 ys = ((ulonglong2*)yswd[ky])[h];
      FMA2(acc[2 * h],     yv.x, w1); FMA2(acc[2 * h],     ys.x, w2);
      FMA2(acc[2 * h + 1], yv.y, w1); FMA2(acc[2 * h + 1], ys.y, w2);
    }
    p += y; if (p >= NSZ) p -= NSZ;
  }

  u64* dst = &Y1g[(line * NSZ + y) * 16];
#pragma unroll
  for (int h = 0; h < 8; h++)
    ((ulonglong2*)dst)[h] = make_ulonglong2(acc[2 * h], acc[2 * h + 1]);
}

// ---------------- I3: inverse z C2R (packed pair accumulate) -----------------
// accpair += Y * (a*c, -a*s); out = lo + hi.
__global__ void __launch_bounds__(256) k_i3(float* __restrict__ out) {
  __shared__ __align__(16) u64 ys[64][16];     // 8 KB
  __shared__ u64 twz[16][192];                 // 24 KB
  size_t rowBase = (size_t)blockIdx.x * 64;
  int tid = threadIdx.x;
  int tx = tid & 31, ty = tid >> 5;

  for (int i = tid; i < 512; i += 256)
    ((ulonglong2*)ys)[i] = ((const ulonglong2*)&Y1g[rowBase * 16])[i];

  const float inv = 1.0f / (192.0f * 192.0f * 192.0f);
  for (int i = tid; i < 16 * 192; i += 256) {
    int k = i / 192, z = i % 192;
    int p = (k * z) % NSZ;
    float2 t = Tm[p];
    float a = (k == 0) ? inv : 2.0f * inv;
    twz[k][z] = pk2(a * t.x, -a * t.y);
  }
  __syncthreads();

  u64 acc[8][6];
#pragma unroll
  for (int j = 0; j < 8; j++)
#pragma unroll
    for (int m = 0; m < 6; m++) acc[j][m] = 0ULL;

#pragma unroll 2
  for (int k = 0; k < 16; k++) {
    u64 tw[6];
#pragma unroll
    for (int m = 0; m < 6; m++) tw[m] = twz[k][tx + 32 * m];
#pragma unroll
    for (int j = 0; j < 8; j++) {
      u64 yv = ys[ty * 8 + j][k];
#pragma unroll
      for (int m = 0; m < 6; m++) FMA2(acc[j][m], yv, tw[m]);
    }
  }
#pragma unroll
  for (int j = 0; j < 8; j++) {
    size_t ob = (rowBase + ty * 8 + j) * NSZ + tx;
#pragma unroll
    for (int m = 0; m < 6; m++) {
      float lo, hi; up2(acc[j][m], lo, hi);
      out[ob + 32 * m] = lo + hi;
    }
  }
}

// ---------------- launch ------------------------------------------------------
extern "C" void kernel_launch(void* const* d_in, const int* in_sizes, int n_in,
                              void* d_out, int out_size) {
  (void)in_sizes; (void)n_in; (void)out_size;
  const float* x  = (const float*)d_in[0];
  const float* wr = (const float*)d_in[1];
  const float* wi = (const float*)d_in[2];

  k_init<<<1, 192>>>();
  k_s1 <<<NROW / 256, 128>>>(x);
  k_s2 <<<NLINE / 4, 128>>>();
  k_s3 <<<NC * MXY, 128>>>();
  k_mix<<<MXY * MXY, 256>>>(wr, wi);
  k_i1 <<<NC * MXY, 192>>>();
  k_i2 <<<NLINE, 192>>>();
  k_i3 <<<NROW / 64, 256>>>((float*)d_out);
}

// round 13
// speedup vs baseline: 1.0941x; 1.0941x over previous
#include <cuda_runtime.h>
#include <math.h>

typedef unsigned long long u64;

#define NSZ 192
#define NC  16
#define MXY 32
#define NLINE (NC*NSZ)       // 3072
#define NROW  (NC*NSZ*NSZ)   // 589824

// ---------------- packed f32x2 helpers --------------------------------------
__device__ __forceinline__ u64 pk2(float lo, float hi) {
  u64 r; asm("mov.b64 %0, {%1, %2};" : "=l"(r) : "f"(lo), "f"(hi)); return r;
}
__device__ __forceinline__ void up2(u64 v, float& lo, float& hi) {
  asm("mov.b64 {%0, %1}, %2;" : "=f"(lo), "=f"(hi) : "l"(v));
}
__device__ __forceinline__ u64 sw2(u64 v) {
  float a, b; up2(v, a, b); return pk2(b, a);
}
#define FMA2(d, a, b) asm("fma.rn.f32x2 %0, %1, %2, %0;" : "+l"(d) : "l"(a), "l"(b))
__device__ __forceinline__ u64 add2(u64 a, u64 b) {
  u64 d; asm("add.rn.f32x2 %0, %1, %2;" : "=l"(d) : "l"(a), "l"(b)); return d;
}
// combine two-accumulator complex sum: A + swap(B)
__device__ __forceinline__ u64 comb(u64 A, u64 B) { return add2(A, sw2(B)); }

// ---------------- twiddle tables ---------------------------------------------
static __device__ float2 Tm[NSZ];
static __device__ u64 fw1g[NSZ], fw2g[NSZ];   // forward:  (c,c), (-s, s)
static __device__ u64 iv1g[NSZ], iv2g[NSZ];   // inverse:  (c,c), ( s,-s)

// ---------------- scratch -----------------------------------------------------
static __device__ __align__(16) u64 X1g[(size_t)NROW * 16];
static __device__ __align__(16) u64 X2g[(size_t)NLINE * MXY * 16];
static __device__ __align__(16) u64 X3g[(size_t)NC * MXY * MXY * 16];
static __device__ __align__(16) u64 Y3g[(size_t)NC * MXY * MXY * 16];
static __device__ __align__(16) u64 Y2g[(size_t)NLINE * MXY * 16];
static __device__ __align__(16) u64 Y1g[(size_t)NROW * 16];

__device__ __forceinline__ int kmap(int j) { return j < 16 ? j : j + 160; }

// ---------------- init ---------------------------------------------------------
__global__ void k_init() {
  int p = threadIdx.x;
  if (p < NSZ) {
    float s, c;
    sincosf(6.283185307179586f * (float)p / 192.0f, &s, &c);
    Tm[p] = make_float2(c, s);
    fw1g[p] = pk2(c, c);  fw2g[p] = pk2(-s, s);
    iv1g[p] = pk2(c, c);  iv2g[p] = pk2(s, -s);
  }
}

// ---------------- S1: z-DFT, real -> 16 complex modes ------------------------
// acc(re,im) += (x,x) * (c,-s): one FFMA2 per (z,kz) term, no swap needed.
// block: 128 thr, 256 rows; thread = (tx:4 kz-quads, ty:32) x 8 rows
__global__ void __launch_bounds__(128) k_s1(const float* __restrict__ xg) {
  __shared__ float xs[32 * 257];
  __shared__ u64 tws[32][16];          // (c, -s)
  int tid = threadIdx.x;
  int tx = tid & 3, ty = tid >> 2;
  int rowBase = blockIdx.x * 256;

  u64 acc[8][4];
#pragma unroll
  for (int j = 0; j < 8; j++)
#pragma unroll
    for (int q = 0; q < 4; q++) acc[j][q] = 0ULL;

  for (int zc = 0; zc < NSZ; zc += 32) {
    __syncthreads();
    for (int i = tid; i < 32 * 16; i += 128) {
      int zl = i >> 4, kz = i & 15;
      int p = (kz * (zc + zl)) % NSZ;
      float2 t = Tm[p];
      tws[zl][kz] = pk2(t.x, -t.y);
    }
    for (int i = tid; i < 256 * 8; i += 128) {
      int row = i >> 3, u = i & 7;
      float4 v = *(const float4*)(xg + (size_t)(rowBase + row) * NSZ + zc + 4 * u);
      int kb = 4 * u;
      xs[(kb + 0) * 257 + row] = v.x;
      xs[(kb + 1) * 257 + row] = v.y;
      xs[(kb + 2) * 257 + row] = v.z;
      xs[(kb + 3) * 257 + row] = v.w;
    }
    __syncthreads();
#pragma unroll 4
    for (int kk = 0; kk < 32; kk++) {
      u64 t0 = tws[kk][4 * tx + 0];
      u64 t1 = tws[kk][4 * tx + 1];
      u64 t2 = tws[kk][4 * tx + 2];
      u64 t3 = tws[kk][4 * tx + 3];
      const float* xr = &xs[kk * 257 + ty];
#pragma unroll
      for (int j = 0; j < 8; j++) {
        float xv = xr[32 * j];
        u64 xb = pk2(xv, xv);
        FMA2(acc[j][0], xb, t0);
        FMA2(acc[j][1], xb, t1);
        FMA2(acc[j][2], xb, t2);
        FMA2(acc[j][3], xb, t3);
      }
    }
  }
#pragma unroll
  for (int j = 0; j < 8; j++) {
    size_t base = (size_t)(rowBase + ty + 32 * j) * 16 + 4 * tx;
    ((ulonglong2*)&X1g[base])[0] = make_ulonglong2(acc[j][0], acc[j][1]);
    ((ulonglong2*)&X1g[base])[1] = make_ulonglong2(acc[j][2], acc[j][3]);
  }
}

// ---------------- S2: y-DFT, complex, 32 ky modes ------------------------------
// two-accumulator FFMA2: A += x*(c,c); B += x*(-s,s); out = A + swap(B)
// block: 128 thr = 4 lines x (8 kyg x 4 kzg); thread tile 4 ky x 4 kz
__global__ void __launch_bounds__(128) k_s2() {
  __shared__ __align__(16) u64 x1s[4][48][16];   // 24 KB
  __shared__ u64 tw1s[48][32], tw2s[48][32];     // 24 KB
  int tid = threadIdx.x;
  int l = tid >> 5, lane = tid & 31;
  int kyg = lane >> 2, kzg = lane & 3;
  int lineBase = blockIdx.x * 4;

  u64 accA[4][4], accB[4][4];
#pragma unroll
  for (int a = 0; a < 4; a++)
#pragma unroll
    for (int b = 0; b < 4; b++) { accA[a][b] = 0ULL; accB[a][b] = 0ULL; }

  for (int yc = 0; yc < NSZ; yc += 48) {
    __syncthreads();
    for (int i = tid; i < 48 * 32; i += 128) {
      int yl = i >> 5, ky = i & 31;
      int p = (kmap(ky) * (yc + yl)) % NSZ;
      tw1s[yl][ky] = fw1g[p];
      tw2s[yl][ky] = fw2g[p];
    }
    for (int i = tid; i < 4 * 48 * 8; i += 128) {
      int li = i / 384, rem = i % 384;
      int yl = rem >> 3, u = rem & 7;
      ((ulonglong2*)x1s[li][yl])[u] =
          ((const ulonglong2*)&X1g[((size_t)(lineBase + li) * NSZ + yc + yl) * 16])[u];
    }
    __syncthreads();
#pragma unroll 4
    for (int yy = 0; yy < 48; yy++) {
      ulonglong2 xa = ((ulonglong2*)&x1s[l][yy][4 * kzg])[0];
      ulonglong2 xb = ((ulonglong2*)&x1s[l][yy][4 * kzg])[1];
#pragma unroll
      for (int a = 0; a < 4; a++) {
        u64 w1 = tw1s[yy][4 * kyg + a];
        u64 w2 = tw2s[yy][4 * kyg + a];
        FMA2(accA[a][0], xa.x, w1); FMA2(accB[a][0], xa.x, w2);
        FMA2(accA[a][1], xa.y, w1); FMA2(accB[a][1], xa.y, w2);
        FMA2(accA[a][2], xb.x, w1); FMA2(accB[a][2], xb.x, w2);
        FMA2(accA[a][3], xb.y, w1); FMA2(accB[a][3], xb.y, w2);
      }
    }
  }
#pragma unroll
  for (int a = 0; a < 4; a++) {
    size_t base = ((size_t)(lineBase + l) * MXY + 4 * kyg + a) * 16 + 4 * kzg;
    ((ulonglong2*)&X2g[base])[0] =
        make_ulonglong2(comb(accA[a][0], accB[a][0]), comb(accA[a][1], accB[a][1]));
    ((ulonglong2*)&X2g[base])[1] =
        make_ulonglong2(comb(accA[a][2], accB[a][2]), comb(accA[a][3], accB[a][3]));
  }
}

// ---------------- S3: x-DFT, complex, 32 kx modes ------------------------------
// block per (c,ky): 256 thr = kx(32) x kzp(8 pairs of kz)
__global__ void __launch_bounds__(256) k_s3() {
  __shared__ __align__(16) u64 x2s[192][16];     // 24 KB
  __shared__ u64 tw1l[NSZ], tw2l[NSZ];           // 3 KB
  int c = blockIdx.x >> 5, ky = blockIdx.x & 31;
  int tid = threadIdx.x;
  int kx = tid & 31, kzp = tid >> 5;

  for (int i = tid; i < NSZ; i += 256) { tw1l[i] = fw1g[i]; tw2l[i] = fw2g[i]; }
  for (int i = tid; i < 192 * 8; i += 256) {
    int xx = i >> 3, u = i & 7;
    ((ulonglong2*)x2s[xx])[u] =
        ((const ulonglong2*)&X2g[(((size_t)c * NSZ + xx) * MXY + ky) * 16])[u];
  }
  __syncthreads();

  int kf = kmap(kx), p = 0;
  u64 A0 = 0, A1 = 0, B0 = 0, B1 = 0;
#pragma unroll 4
  for (int xx = 0; xx < NSZ; xx++) {
    u64 w1 = tw1l[p], w2 = tw2l[p];
    ulonglong2 v = ((ulonglong2*)&x2s[xx][2 * kzp])[0];
    FMA2(A0, v.x, w1); FMA2(B0, v.x, w2);
    FMA2(A1, v.y, w1); FMA2(B1, v.y, w2);
    p += kf; if (p >= NSZ) p -= NSZ;
  }
  size_t base = (((size_t)c * MXY + kx) * MXY + ky) * 16 + 2 * kzp;
  ((ulonglong2*)&X3g[base])[0] = make_ulonglong2(comb(A0, B0), comb(A1, B1));
}

// ---------------- Mix: 16x16 complex channel mix -------------------------------
// A += x*(wr,wr); B += x*(wi,-wi); out = A + swap(B)
__global__ void __launch_bounds__(256) k_mix(const float* __restrict__ wr,
                                             const float* __restrict__ wi) {
  __shared__ u64 xin[16][16];
  int kx = blockIdx.x >> 5, ky = blockIdx.x & 31;
  int tid = threadIdx.x;
  int kz = tid & 15, o = tid >> 4;
  {
    int i = tid >> 4, z = tid & 15;
    xin[i][z] = X3g[(((size_t)i * MXY + kx) * MXY + ky) * 16 + z];
  }
  __syncthreads();
  int q = (kx >= 16 ? 1 : 0) + (ky >= 16 ? 2 : 0);
  int mx = kx & 15, my = ky & 15;
  int moff = mx * 256 + my * 16 + kz;
  u64 A = 0, B = 0;
#pragma unroll
  for (int i = 0; i < 16; i++) {
    int widx = ((q * 16 + i) * 16 + o) * 4096 + moff;
    float wrv = wr[widx], wiv = wi[widx];
    u64 xv = xin[i][kz];
    FMA2(A, xv, pk2(wrv, wrv));
    FMA2(B, xv, pk2(wiv, -wiv));
  }
  Y3g[(((size_t)o * MXY + kx) * MXY + ky) * 16 + kz] = comb(A, B);
}

// ---------------- I1: inverse x (32 modes -> 192 x) ----------------------------
// block per (c,ky) = 512 blocks; 192 thr, thread = x; 16 packed kz accs (A/B).
__global__ void __launch_bounds__(192) k_i1() {
  __shared__ __align__(16) u64 ysd[32][16];      // 4 KB
  __shared__ u64 tw1l[NSZ], tw2l[NSZ];           // 3 KB
  int c = blockIdx.x >> 5, ky = blockIdx.x & 31;
  int x = threadIdx.x;

  if (x < NSZ) { tw1l[x] = iv1g[x]; tw2l[x] = iv2g[x]; }
  for (int i = x; i < 512; i += 192)
    ysd[i >> 4][i & 15] = Y3g[(((size_t)c * MXY + (i >> 4)) * MXY + ky) * 16 + (i & 15)];
  __syncthreads();

  u64 accA[16], accB[16];
#pragma unroll
  for (int z = 0; z < 16; z++) { accA[z] = 0ULL; accB[z] = 0ULL; }

  int p = 0;
#pragma unroll 2
  for (int kx = 0; kx < 16; kx++) {
    u64 w1 = tw1l[p], w2 = tw2l[p];
#pragma unroll
    for (int h = 0; h < 8; h++) {
      ulonglong2 y = ((ulonglong2*)ysd[kx])[h];
      FMA2(accA[2 * h],     y.x, w1); FMA2(accB[2 * h],     y.x, w2);
      FMA2(accA[2 * h + 1], y.y, w1); FMA2(accB[2 * h + 1], y.y, w2);
    }
    p += x; if (p >= NSZ) p -= NSZ;
  }
  p = (176 * x) % NSZ;
#pragma unroll 2
  for (int kx = 16; kx < 32; kx++) {
    u64 w1 = tw1l[p], w2 = tw2l[p];
#pragma unroll
    for (int h = 0; h < 8; h++) {
      ulonglong2 y = ((ulonglong2*)ysd[kx])[h];
      FMA2(accA[2 * h],     y.x, w1); FMA2(accB[2 * h],     y.x, w2);
      FMA2(accA[2 * h + 1], y.y, w1); FMA2(accB[2 * h + 1], y.y, w2);
    }
    p += x; if (p >= NSZ) p -= NSZ;
  }

  u64* dst = &Y2g[(((size_t)c * NSZ + x) * MXY + ky) * 16];
#pragma unroll
  for (int h = 0; h < 8; h++)
    ((ulonglong2*)dst)[h] =
        make_ulonglong2(comb(accA[2 * h], accB[2 * h]),
                        comb(accA[2 * h + 1], accB[2 * h + 1]));
}

// ---------------- I2: inverse y (32 modes -> 192 y) ----------------------------
// block per line (c,x) = 3072 blocks; 192 thr, thread = y.
__global__ void __launch_bounds__(192) k_i2() {
  __shared__ __align__(16) u64 ysd[32][16];
  __shared__ u64 tw1l[NSZ], tw2l[NSZ];
  size_t line = (size_t)blockIdx.x;
  int y = threadIdx.x;

  if (y < NSZ) { tw1l[y] = iv1g[y]; tw2l[y] = iv2g[y]; }
  for (int i = y; i < 512; i += 192)
    ysd[i >> 4][i & 15] = Y2g[line * 512 + i];
  __syncthreads();

  u64 accA[16], accB[16];
#pragma unroll
  for (int z = 0; z < 16; z++) { accA[z] = 0ULL; accB[z] = 0ULL; }

  int p = 0;
#pragma unroll 2
  for (int ky = 0; ky < 16; ky++) {
    u64 w1 = tw1l[p], w2 = tw2l[p];
#pragma unroll
    for (int h = 0; h < 8; h++) {
      ulonglong2 yv = ((ulonglong2*)ysd[ky])[h];
      FMA2(accA[2 * h],     yv.x, w1); FMA2(accB[2 * h],     yv.x, w2);
      FMA2(accA[2 * h + 1], yv.y, w1); FMA2(accB[2 * h + 1], yv.y, w2);
    }
    p += y; if (p >= NSZ) p -= NSZ;
  }
  p = (176 * y) % NSZ;
#pragma unroll 2
  for (int ky = 16; ky < 32; ky++) {
    u64 w1 = tw1l[p], w2 = tw2l[p];
#pragma unroll
    for (int h = 0; h < 8; h++) {
      ulonglong2 yv = ((ulonglong2*)ysd[ky])[h];
      FMA2(accA[2 * h],     yv.x, w1); FMA2(accB[2 * h],     yv.x, w2);
      FMA2(accA[2 * h + 1], yv.y, w1); FMA2(accB[2 * h + 1], yv.y, w2);
    }
    p += y; if (p >= NSZ) p -= NSZ;
  }

  u64* dst = &Y1g[(line * NSZ + y) * 16];
#pragma unroll
  for (int h = 0; h < 8; h++)
    ((ulonglong2*)dst)[h] =
        make_ulonglong2(comb(accA[2 * h], accB[2 * h]),
                        comb(accA[2 * h + 1], accB[2 * h + 1]));
}

// ---------------- I3: inverse z C2R (packed pair accumulate) --------------------
// accpair += Y * (a*c, -a*s); out = lo + hi. One FFMA2 per term.
// block: 256 thr = tx(32 z-lanes) x ty(8); 32 rows/block, thread tile 4 rows x 6 z
__global__ void __launch_bounds__(256) k_i3(float* __restrict__ out) {
  __shared__ __align__(16) u64 ys[32][16];       // 4 KB
  __shared__ u64 twz[16][192];                   // 24 KB
  size_t rowBase = (size_t)blockIdx.x * 32;
  int tid = threadIdx.x;
  int tx = tid & 31, ty = tid >> 5;

  for (int i = tid; i < 256; i += 256)
    ((ulonglong2*)ys)[i] = ((const ulonglong2*)&Y1g[rowBase * 16])[i];

  const float inv = 1.0f / (192.0f * 192.0f * 192.0f);
  for (int i = tid; i < 16 * 192; i += 256) {
    int k = i / 192, z = i % 192;
    int p = (k * z) % NSZ;
    float2 t = Tm[p];
    float a = (k == 0) ? inv : 2.0f * inv;
    twz[k][z] = pk2(a * t.x, -a * t.y);
  }
  __syncthreads();

  u64 acc[4][6];
#pragma unroll
  for (int j = 0; j < 4; j++)
#pragma unroll
    for (int m = 0; m < 6; m++) acc[j][m] = 0ULL;

#pragma unroll 4
  for (int k = 0; k < 16; k++) {
    u64 tw[6];
#pragma unroll
    for (int m = 0; m < 6; m++) tw[m] = twz[k][tx + 32 * m];
#pragma unroll
    for (int j = 0; j < 4; j++) {
      u64 yv = ys[ty * 4 + j][k];
#pragma unroll
      for (int m = 0; m < 6; m++) FMA2(acc[j][m], yv, tw[m]);
    }
  }
#pragma unroll
  for (int j = 0; j < 4; j++) {
    size_t ob = (rowBase + ty * 4 + j) * NSZ + tx;
#pragma unroll
    for (int m = 0; m < 6; m++) {
      float lo, hi; up2(acc[j][m], lo, hi);
      out[ob + 32 * m] = lo + hi;
    }
  }
}

// ---------------- launch ---------------------------------------------------------
extern "C" void kernel_launch(void* const* d_in, const int* in_sizes, int n_in,
                              void* d_out, int out_size) {
  (void)in_sizes; (void)n_in; (void)out_size;
  const float* x  = (const float*)d_in[0];
  const float* wr = (const float*)d_in[1];
  const float* wi = (const float*)d_in[2];

  k_init<<<1, 192>>>();
  k_s1 <<<NROW / 256, 128>>>(x);            // 2304 blocks
  k_s2 <<<NLINE / 4, 128>>>();              // 768 blocks
  k_s3 <<<NC * MXY, 256>>>();               // 512 blocks
  k_mix<<<MXY * MXY, 256>>>(wr, wi);        // 1024 blocks
  k_i1 <<<NC * MXY, 192>>>();               // 512 blocks
  k_i2 <<<NLINE, 192>>>();                  // 3072 blocks
  k_i3 <<<NROW / 32, 256>>>((float*)d_out); // 18432 blocks
}

// round 14
// speedup vs baseline: 1.6598x; 1.5171x over previous
#include <cuda_runtime.h>
#include <math.h>

#define NSZ 192
#define NC  16
#define MXY 32
#define NLINE (NC*NSZ)       // 3072
#define NROW  (NC*NSZ*NSZ)   // 589824

// ---------------- twiddle master table + scratch -----------------------------
static __device__ float2 Tm[NSZ];   // (cos, sin) of 2*pi*p/192

static __device__ __align__(16) float2 X1g[(size_t)NROW * 16];            // (c,x,y,kz)
static __device__ __align__(16) float2 X2g[(size_t)NLINE * MXY * 16];     // (c,x,ky,kz)
static __device__ __align__(16) float2 X3g[(size_t)NC * MXY * MXY * 16];  // (i,kx,ky,kz)
static __device__ __align__(16) float2 Y3g[(size_t)NC * MXY * MXY * 16];  // (o,kx,ky,kz)
static __device__ __align__(16) float2 Y2g[(size_t)NLINE * MXY * 16];     // (c,x,ky,kz)
static __device__ __align__(16) float2 Y1g[(size_t)NROW * 16];            // (c,x,y,kz)

__device__ __forceinline__ int kmap(int j) { return j < 16 ? j : j + 160; }

__global__ void k_init() {
  int p = threadIdx.x;
  if (p < NSZ) {
    float s, c;
    sincosf(6.283185307179586f * (float)p / 192.0f, &s, &c);
    Tm[p] = make_float2(c, s);
  }
}

// ---------------- S1: z-DFT, real -> 16 complex modes, radix-2 folded --------
// X[k] = sum_{z<96} v[z] * e^{-2i pi k z/192}, v = x[z]+x[z+96] (k even) else diff.
// block: 128 thr, 256 rows; thread = (tx: k-quad {4tx..4tx+3}, ty: 32) x 8 rows
__global__ void __launch_bounds__(128) k_s1(const float* __restrict__ xg) {
  __shared__ float ss[16][257];        // sum   [z_local][row]
  __shared__ float dd[16][257];        // diff
  __shared__ float2 tws[16][16];       // (cos, sin) [z_local][k]
  int tid = threadIdx.x;
  int tx = tid & 3, ty = tid >> 2;
  int rowBase = blockIdx.x * 256;

  float2 acc[8][4];
#pragma unroll
  for (int j = 0; j < 8; j++)
#pragma unroll
    for (int q = 0; q < 4; q++) acc[j][q] = make_float2(0.f, 0.f);

  for (int zc = 0; zc < 96; zc += 16) {
    __syncthreads();
    for (int i = tid; i < 256; i += 128) {
      int zl = i >> 4, k = i & 15;
      int p = (k * (zc + zl)) % NSZ;
      tws[zl][k] = Tm[p];
    }
    for (int i = tid; i < 1024; i += 128) {   // 256 rows x 4 float4
      int row = i >> 2, u = i & 3;
      const float* rp = xg + (size_t)(rowBase + row) * NSZ + zc + 4 * u;
      float4 a = *(const float4*)rp;
      float4 b = *(const float4*)(rp + 96);
      int zb = 4 * u;
      ss[zb + 0][row] = a.x + b.x;  dd[zb + 0][row] = a.x - b.x;
      ss[zb + 1][row] = a.y + b.y;  dd[zb + 1][row] = a.y - b.y;
      ss[zb + 2][row] = a.z + b.z;  dd[zb + 2][row] = a.z - b.z;
      ss[zb + 3][row] = a.w + b.w;  dd[zb + 3][row] = a.w - b.w;
    }
    __syncthreads();
#pragma unroll 4
    for (int zl = 0; zl < 16; zl++) {
      float2 t0 = tws[zl][4 * tx + 0];
      float2 t1 = tws[zl][4 * tx + 1];
      float2 t2 = tws[zl][4 * tx + 2];
      float2 t3 = tws[zl][4 * tx + 3];
      const float* sr = &ss[zl][ty];
      const float* dr = &dd[zl][ty];
#pragma unroll
      for (int j = 0; j < 8; j++) {
        float sv = sr[32 * j], dv = dr[32 * j];
        acc[j][0].x += sv * t0.x;  acc[j][0].y -= sv * t0.y;   // k even
        acc[j][1].x += dv * t1.x;  acc[j][1].y -= dv * t1.y;   // k odd
        acc[j][2].x += sv * t2.x;  acc[j][2].y -= sv * t2.y;
        acc[j][3].x += dv * t3.x;  acc[j][3].y -= dv * t3.y;
      }
    }
  }
#pragma unroll
  for (int j = 0; j < 8; j++) {
    size_t base = (size_t)(rowBase + ty + 32 * j) * 16 + 4 * tx;
    ((float4*)&X1g[base])[0] = make_float4(acc[j][0].x, acc[j][0].y, acc[j][1].x, acc[j][1].y);
    ((float4*)&X1g[base])[1] = make_float4(acc[j][2].x, acc[j][2].y, acc[j][3].x, acc[j][3].y);
  }
}

// ---------------- S2: y-DFT, complex, 32 ky modes, folded --------------------
// block: 128 thr = 4 lines x (kyg 8 x kzg 4); thread tile 4 ky x 4 kz
__global__ void __launch_bounds__(128) k_s2() {
  __shared__ __align__(16) float2 sA[4][24][16];   // sum
  __shared__ __align__(16) float2 dA[4][24][16];   // diff
  __shared__ float2 twy[24][32];
  int tid = threadIdx.x;
  int l = tid >> 5, lane = tid & 31;
  int kyg = lane >> 2, kzg = lane & 3;
  int lineBase = blockIdx.x * 4;

  float2 acc[4][4];
#pragma unroll
  for (int a = 0; a < 4; a++)
#pragma unroll
    for (int b = 0; b < 4; b++) acc[a][b] = make_float2(0.f, 0.f);

  for (int yc = 0; yc < 96; yc += 24) {
    __syncthreads();
    for (int i = tid; i < 24 * 32; i += 128) {
      int yl = i >> 5, ky = i & 31;
      int p = (kmap(ky) * (yc + yl)) % NSZ;
      twy[yl][ky] = Tm[p];
    }
    for (int i = tid; i < 4 * 24 * 8; i += 128) {
      int li = i / 192, r = i % 192;
      int yl = r >> 3, u = r & 7;
      const float4* pa = (const float4*)&X1g[((size_t)(lineBase + li) * NSZ + yc + yl) * 16];
      const float4* pb = (const float4*)&X1g[((size_t)(lineBase + li) * NSZ + yc + 96 + yl) * 16];
      float4 a = pa[u], b = pb[u];
      ((float4*)&sA[li][yl][0])[u] = make_float4(a.x + b.x, a.y + b.y, a.z + b.z, a.w + b.w);
      ((float4*)&dA[li][yl][0])[u] = make_float4(a.x - b.x, a.y - b.y, a.z - b.z, a.w - b.w);
    }
    __syncthreads();
#pragma unroll 4
    for (int yl = 0; yl < 24; yl++) {
      float2 sv[4], dv[4];
      ((float4*)sv)[0] = ((float4*)&sA[l][yl][4 * kzg])[0];
      ((float4*)sv)[1] = ((float4*)&sA[l][yl][4 * kzg])[1];
      ((float4*)dv)[0] = ((float4*)&dA[l][yl][4 * kzg])[0];
      ((float4*)dv)[1] = ((float4*)&dA[l][yl][4 * kzg])[1];
#pragma unroll
      for (int a = 0; a < 4; a++) {
        float2 t = twy[yl][4 * kyg + a];
        const float2* v = (a & 1) ? dv : sv;   // ky parity = a parity
#pragma unroll
        for (int b = 0; b < 4; b++) {
          acc[a][b].x += t.x * v[b].x + t.y * v[b].y;
          acc[a][b].y += t.x * v[b].y - t.y * v[b].x;
        }
      }
    }
  }
#pragma unroll
  for (int a = 0; a < 4; a++) {
    size_t base = ((size_t)(lineBase + l) * MXY + 4 * kyg + a) * 16 + 4 * kzg;
    ((float4*)&X2g[base])[0] = make_float4(acc[a][0].x, acc[a][0].y, acc[a][1].x, acc[a][1].y);
    ((float4*)&X2g[base])[1] = make_float4(acc[a][2].x, acc[a][2].y, acc[a][3].x, acc[a][3].y);
  }
}

// ---------------- S3: x-DFT, complex, 32 kx modes, folded --------------------
// block per (c,ky): 256 thr = kx(32) x kzp(8 kz-pairs)
__global__ void __launch_bounds__(256) k_s3() {
  __shared__ __align__(16) float2 sA[96][16];
  __shared__ __align__(16) float2 dA[96][16];
  __shared__ float2 Tml[NSZ];
  int c = blockIdx.x >> 5, ky = blockIdx.x & 31;
  int tid = threadIdx.x;
  int kx = tid & 31, kzp = tid >> 5;

  for (int i = tid; i < NSZ; i += 256) Tml[i] = Tm[i];
  for (int i = tid; i < 96 * 8; i += 256) {
    int xx = i >> 3, u = i & 7;
    float4 a = ((const float4*)&X2g[(((size_t)c * NSZ + xx) * MXY + ky) * 16])[u];
    float4 b = ((const float4*)&X2g[(((size_t)c * NSZ + xx + 96) * MXY + ky) * 16])[u];
    ((float4*)&sA[xx][0])[u] = make_float4(a.x + b.x, a.y + b.y, a.z + b.z, a.w + b.w);
    ((float4*)&dA[xx][0])[u] = make_float4(a.x - b.x, a.y - b.y, a.z - b.z, a.w - b.w);
  }
  __syncthreads();

  const float2* vb = (kx & 1) ? &dA[0][0] : &sA[0][0];
  int kf = kmap(kx), p = 0;
  float2 a0 = make_float2(0.f, 0.f), a1 = make_float2(0.f, 0.f);
#pragma unroll 4
  for (int xx = 0; xx < 96; xx++) {
    float2 t = Tml[p];
    float4 v = *(const float4*)(vb + xx * 16 + 2 * kzp);
    a0.x += t.x * v.x + t.y * v.y;  a0.y += t.x * v.y - t.y * v.x;
    a1.x += t.x * v.z + t.y * v.w;  a1.y += t.x * v.w - t.y * v.z;
    p += kf; if (p >= NSZ) p -= NSZ;
  }
  size_t base = (((size_t)c * MXY + kx) * MXY + ky) * 16 + 2 * kzp;
  ((float4*)&X3g[base])[0] = make_float4(a0.x, a0.y, a1.x, a1.y);
}

// ---------------- Mix: per-mode 16x16 complex channel mix --------------------
__global__ void __launch_bounds__(256) k_mix(const float* __restrict__ wr,
                                             const float* __restrict__ wi) {
  __shared__ float2 xin[16][16];
  int kx = blockIdx.x >> 5, ky = blockIdx.x & 31;
  int tid = threadIdx.x;
  int kz = tid & 15, o = tid >> 4;
  {
    int i = tid >> 4, z = tid & 15;
    xin[i][z] = X3g[(((size_t)i * MXY + kx) * MXY + ky) * 16 + z];
  }
  __syncthreads();
  int q = (kx >= 16 ? 1 : 0) + (ky >= 16 ? 2 : 0);
  int mx = kx & 15, my = ky & 15;
  int moff = mx * 256 + my * 16 + kz;
  float2 acc = make_float2(0.f, 0.f);
#pragma unroll
  for (int i = 0; i < 16; i++) {
    int widx = ((q * 16 + i) * 16 + o) * 4096 + moff;
    float wrv = wr[widx], wiv = wi[widx];
    float2 xv = xin[i][kz];
    acc.x += xv.x * wrv - xv.y * wiv;
    acc.y += xv.x * wiv + xv.y * wrv;
  }
  Y3g[(((size_t)o * MXY + kx) * MXY + ky) * 16 + kz] = acc;
}

// ---------------- I1: inverse x (32 modes -> 192 x), even/odd folded ---------
// block per (c, ky-pair): 192 thr = 2 ky x 96 x-positions
__global__ void __launch_bounds__(192) k_i1() {
  __shared__ __align__(16) float2 ysd[2][32][16];
  __shared__ float2 Tml[NSZ];
  int c = blockIdx.x >> 4, kyp = blockIdx.x & 15;
  int tid = threadIdx.x;
  int h = tid / 96, x = tid % 96;
  int ky = 2 * kyp + h;

  for (int i = tid; i < NSZ; i += 192) Tml[i] = Tm[i];
  for (int i = tid; i < 1024; i += 192) {
    int hh = i >> 9, r = i & 511;
    ysd[hh][r >> 4][r & 15] =
        Y3g[(((size_t)c * MXY + (r >> 4)) * MXY + (2 * kyp + hh)) * 16 + (r & 15)];
  }
  __syncthreads();

  float2 E[16], O[16];
#pragma unroll
  for (int z = 0; z < 16; z++) { E[z] = make_float2(0.f, 0.f); O[z] = make_float2(0.f, 0.f); }

  int p = 0;
#pragma unroll 2
  for (int kx = 0; kx < 16; kx += 2) {
    float2 te = Tml[p];
    int p2 = p + x; if (p2 >= NSZ) p2 -= NSZ;
    float2 to = Tml[p2];
    p = p2 + x; if (p >= NSZ) p -= NSZ;
    const float4* ye = (const float4*)&ysd[h][kx][0];
    const float4* yo = (const float4*)&ysd[h][kx + 1][0];
#pragma unroll
    for (int qq = 0; qq < 8; qq++) {
      float4 a = ye[qq], b = yo[qq];
      E[2*qq].x   += te.x*a.x - te.y*a.y;  E[2*qq].y   += te.x*a.y + te.y*a.x;
      E[2*qq+1].x += te.x*a.z - te.y*a.w;  E[2*qq+1].y += te.x*a.w + te.y*a.z;
      O[2*qq].x   += to.x*b.x - to.y*b.y;  O[2*qq].y   += to.x*b.y + to.y*b.x;
      O[2*qq+1].x += to.x*b.z - to.y*b.w;  O[2*qq+1].y += to.x*b.w + to.y*b.z;
    }
  }
  p = (176 * x) % NSZ;
#pragma unroll 2
  for (int kx = 16; kx < 32; kx += 2) {
    float2 te = Tml[p];
    int p2 = p + x; if (p2 >= NSZ) p2 -= NSZ;
    float2 to = Tml[p2];
    p = p2 + x; if (p >= NSZ) p -= NSZ;
    const float4* ye = (const float4*)&ysd[h][kx][0];
    const float4* yo = (const float4*)&ysd[h][kx + 1][0];
#pragma unroll
    for (int qq = 0; qq < 8; qq++) {
      float4 a = ye[qq], b = yo[qq];
      E[2*qq].x   += te.x*a.x - te.y*a.y;  E[2*qq].y   += te.x*a.y + te.y*a.x;
      E[2*qq+1].x += te.x*a.z - te.y*a.w;  E[2*qq+1].y += te.x*a.w + te.y*a.z;
      O[2*qq].x   += to.x*b.x - to.y*b.y;  O[2*qq].y   += to.x*b.y + to.y*b.x;
      O[2*qq+1].x += to.x*b.z - to.y*b.w;  O[2*qq+1].y += to.x*b.w + to.y*b.z;
    }
  }

  float4* d0 = (float4*)&Y2g[(((size_t)c * NSZ + x) * MXY + ky) * 16];
  float4* d1 = (float4*)&Y2g[(((size_t)c * NSZ + x + 96) * MXY + ky) * 16];
#pragma unroll
  for (int qq = 0; qq < 8; qq++) {
    d0[qq] = make_float4(E[2*qq].x + O[2*qq].x,   E[2*qq].y + O[2*qq].y,
                         E[2*qq+1].x + O[2*qq+1].x, E[2*qq+1].y + O[2*qq+1].y);
    d1[qq] = make_float4(E[2*qq].x - O[2*qq].x,   E[2*qq].y - O[2*qq].y,
                         E[2*qq+1].x - O[2*qq+1].x, E[2*qq+1].y - O[2*qq+1].y);
  }
}

// ---------------- I2: inverse y (32 modes -> 192 y), even/odd folded ---------
// block = 2 lines x 96 y-positions
__global__ void __launch_bounds__(192) k_i2() {
  __shared__ __align__(16) float2 ysd[2][32][16];
  __shared__ float2 Tml[NSZ];
  int tid = threadIdx.x;
  int h = tid / 96, y = tid % 96;
  size_t line = (size_t)blockIdx.x * 2 + h;

  for (int i = tid; i < NSZ; i += 192) Tml[i] = Tm[i];
  for (int i = tid; i < 1024; i += 192) {
    int hh = i >> 9, r = i & 511;
    ysd[hh][r >> 4][r & 15] = Y2g[((size_t)blockIdx.x * 2 + hh) * 512 + r];
  }
  __syncthreads();

  float2 E[16], O[16];
#pragma unroll
  for (int z = 0; z < 16; z++) { E[z] = make_float2(0.f, 0.f); O[z] = make_float2(0.f, 0.f); }

  int p = 0;
#pragma unroll 2
  for (int ky = 0; ky < 16; ky += 2) {
    float2 te = Tml[p];
    int p2 = p + y; if (p2 >= NSZ) p2 -= NSZ;
    float2 to = Tml[p2];
    p = p2 + y; if (p >= NSZ) p -= NSZ;
    const float4* ye = (const float4*)&ysd[h][ky][0];
    const float4* yo = (const float4*)&ysd[h][ky + 1][0];
#pragma unroll
    for (int qq = 0; qq < 8; qq++) {
      float4 a = ye[qq], b = yo[qq];
      E[2*qq].x   += te.x*a.x - te.y*a.y;  E[2*qq].y   += te.x*a.y + te.y*a.x;
      E[2*qq+1].x += te.x*a.z - te.y*a.w;  E[2*qq+1].y += te.x*a.w + te.y*a.z;
      O[2*qq].x   += to.x*b.x - to.y*b.y;  O[2*qq].y   += to.x*b.y + to.y*b.x;
      O[2*qq+1].x += to.x*b.z - to.y*b.w;  O[2*qq+1].y += to.x*b.w + to.y*b.z;
    }
  }
  p = (176 * y) % NSZ;
#pragma unroll 2
  for (int ky = 16; ky < 32; ky += 2) {
    float2 te = Tml[p];
    int p2 = p + y; if (p2 >= NSZ) p2 -= NSZ;
    float2 to = Tml[p2];
    p = p2 + y; if (p >= NSZ) p -= NSZ;
    const float4* ye = (const float4*)&ysd[h][ky][0];
    const float4* yo = (const float4*)&ysd[h][ky + 1][0];
#pragma unroll
    for (int qq = 0; qq < 8; qq++) {
      float4 a = ye[qq], b = yo[qq];
      E[2*qq].x   += te.x*a.x - te.y*a.y;  E[2*qq].y   += te.x*a.y + te.y*a.x;
      E[2*qq+1].x += te.x*a.z - te.y*a.w;  E[2*qq+1].y += te.x*a.w + te.y*a.z;
      O[2*qq].x   += to.x*b.x - to.y*b.y;  O[2*qq].y   += to.x*b.y + to.y*b.x;
      O[2*qq+1].x += to.x*b.z - to.y*b.w;  O[2*qq+1].y += to.x*b.w + to.y*b.z;
    }
  }

  float4* d0 = (float4*)&Y1g[(line * NSZ + y) * 16];
  float4* d1 = (float4*)&Y1g[(line * NSZ + y + 96) * 16];
#pragma unroll
  for (int qq = 0; qq < 8; qq++) {
    d0[qq] = make_float4(E[2*qq].x + O[2*qq].x,   E[2*qq].y + O[2*qq].y,
                         E[2*qq+1].x + O[2*qq+1].x, E[2*qq+1].y + O[2*qq+1].y);
    d1[qq] = make_float4(E[2*qq].x - O[2*qq].x,   E[2*qq].y - O[2*qq].y,
                         E[2*qq+1].x - O[2*qq+1].x, E[2*qq+1].y - O[2*qq+1].y);
  }
}

// ---------------- I3: inverse z C2R with cos/sin z-symmetry ------------------
// C[z] = sum_k a_k Re_k cos(kz), S[z] = sum_k a_k Im_k sin(kz)
// out[z] = C - S (z=0..95), out[192-z] = C + S (z=1..95), out[96] = C96.
// block: 256 thr = tx(32) x ty(8); 64 rows; thread: 8 rows x 3 z + z96
__global__ void __launch_bounds__(256) k_i3(float* __restrict__ out) {
  __shared__ __align__(16) float2 ys[64][16];   // 8 KB
  __shared__ float2 twz[16][97];                // (a*cos, a*sin), 12.1 KB
  size_t rowBase = (size_t)blockIdx.x * 64;
  int tid = threadIdx.x;
  int tx = tid & 31, ty = tid >> 5;

  for (int i = tid; i < 512; i += 256)
    ((float4*)ys)[i] = ((const float4*)&Y1g[rowBase * 16])[i];

  const float inv = 1.0f / (192.0f * 192.0f * 192.0f);
  for (int i = tid; i < 16 * 97; i += 256) {
    int k = i / 97, z = i % 97;
    int p = (k * z) % NSZ;
    float a = (k == 0) ? inv : 2.0f * inv;
    twz[k][z] = make_float2(a * Tm[p].x, a * Tm[p].y);
  }
  __syncthreads();

  float C[8][3], S[8][3], C96[8];
#pragma unroll
  for (int j = 0; j < 8; j++) {
    C96[j] = 0.f;
#pragma unroll
    for (int m = 0; m < 3; m++) { C[j][m] = 0.f; S[j][m] = 0.f; }
  }

#pragma unroll 2
  for (int k = 0; k < 16; k++) {
    float2 t0 = twz[k][tx];
    float2 t1 = twz[k][tx + 32];
    float2 t2 = twz[k][tx + 64];
    float t96 = twz[k][96].x;
#pragma unroll
    for (int j = 0; j < 8; j++) {
      float2 yv = ys[ty * 8 + j][k];
      C[j][0] += yv.x * t0.x;  S[j][0] += yv.y * t0.y;
      C[j][1] += yv.x * t1.x;  S[j][1] += yv.y * t1.y;
      C[j][2] += yv.x * t2.x;  S[j][2] += yv.y * t2.y;
      C96[j]  += yv.x * t96;
    }
  }
#pragma unroll
  for (int j = 0; j < 8; j++) {
    size_t base = (rowBase + ty * 8 + j) * NSZ;
#pragma unroll
    for (int m = 0; m < 3; m++) {
      int z = tx + 32 * m;
      out[base + z] = C[j][m] - S[j][m];
      if (z) out[base + NSZ - z] = C[j][m] + S[j][m];
    }
    if (tx == 0) out[base + 96] = C96[j];
  }
}

// ---------------- launch -------------------------------------------------------
extern "C" void kernel_launch(void* const* d_in, const int* in_sizes, int n_in,
                              void* d_out, int out_size) {
  (void)in_sizes; (void)n_in; (void)out_size;
  const float* x  = (const float*)d_in[0];
  const float* wr = (const float*)d_in[1];
  const float* wi = (const float*)d_in[2];

  k_init<<<1, 192>>>();
  k_s1 <<<NROW / 256, 128>>>(x);            // 2304 blocks
  k_s2 <<<NLINE / 4, 128>>>();              // 768 blocks
  k_s3 <<<NC * MXY, 256>>>();               // 512 blocks
  k_mix<<<MXY * MXY, 256>>>(wr, wi);        // 1024 blocks
  k_i1 <<<NC * 16, 192>>>();                // 256 blocks
  k_i2 <<<NLINE / 2, 192>>>();              // 1536 blocks
  k_i3 <<<NROW / 64, 256>>>((float*)d_out); // 9216 blocks
}